// round 6
// baseline (speedup 1.0000x reference)
#include <cuda_runtime.h>
#include <cstdint>
#include <math.h>

#define SEQ 2048
#define HID 4096
#define KVD 1024
#define NH  32
#define NKV 8
#define HD  128

// Scratch (device globals — no allocation allowed)
__device__ float g_Q[SEQ * HID];   // 32 MB
__device__ float g_K[SEQ * KVD];   // 8 MB
__device__ float g_V[SEQ * KVD];   // 8 MB
__device__ float g_A[SEQ * HID];   // 32 MB (attention output, head-major cols)

// ===========================================================================
// helpers
// ===========================================================================
__device__ __forceinline__ void mma_bf16(float* c, const uint32_t* a, const uint32_t* b) {
    asm volatile(
        "mma.sync.aligned.m16n8k16.row.col.f32.bf16.bf16.f32 "
        "{%0,%1,%2,%3}, {%4,%5,%6,%7}, {%8,%9}, {%0,%1,%2,%3};"
        : "+f"(c[0]), "+f"(c[1]), "+f"(c[2]), "+f"(c[3])
        : "r"(a[0]), "r"(a[1]), "r"(a[2]), "r"(a[3]),
          "r"(b[0]), "r"(b[1]));
}

// pack two floats into bf16x2: x0 -> low half, x1 -> high half
__device__ __forceinline__ uint32_t pack_bf16x2(float x0, float x1) {
    uint32_t d;
    asm("cvt.rn.bf16x2.f32 %0, %1, %2;" : "=r"(d) : "f"(x1), "f"(x0));
    return d;
}
__device__ __forceinline__ float bf16lo_f(uint32_t u) { return __uint_as_float(u << 16); }
__device__ __forceinline__ float bf16hi_f(uint32_t u) { return __uint_as_float(u & 0xffff0000u); }

// convert float4 (4 consecutive k) -> hi pair + lo pair (bf16x2 each)
__device__ __forceinline__ void split4(const float4 v, uint2& hi, uint2& lo) {
    uint32_t h01 = pack_bf16x2(v.x, v.y);
    uint32_t h23 = pack_bf16x2(v.z, v.w);
    uint32_t l01 = pack_bf16x2(v.x - bf16lo_f(h01), v.y - bf16hi_f(h01));
    uint32_t l23 = pack_bf16x2(v.z - bf16lo_f(h23), v.w - bf16hi_f(h23));
    hi = make_uint2(h01, h23);
    lo = make_uint2(l01, l23);
}

// ===========================================================================
// bf16x2 (split-float) mma.sync GEMM:  C[m,n] = sum_k A[m*K+k] * B[n*K+k]
// A ~ A_hi + A_lo in bf16; C = Ah*Bh + Ah*Bl + Al*Bh  (fp32 accum).
// BM=BN=128, BK=32, 2-stage smem + register prefetch, 256 threads
// (2x4 warps, 64x32 warp tile). Requires M%128==0, N%128==0, K%32==0.
// ===========================================================================
static constexpr int PITCH = 18;                      // uint32 per row (32 bf16 = 16 + 2 pad)
static constexpr int TILE_B = 128 * PITCH * 4;        // 9216 bytes per bf16 tile
static constexpr int ST_AHI = 0;
static constexpr int ST_ALO = TILE_B;
static constexpr int ST_BHI = 2 * TILE_B;
static constexpr int ST_BLO = 3 * TILE_B;
static constexpr int STAGE_BYTES = 4 * TILE_B;        // 36864
static constexpr int GEMM_SMEM_BYTES = 2 * STAGE_BYTES;  // 73728

__global__ __launch_bounds__(256) void mma_gemm_bf16x2(const float* __restrict__ A,
                                                       const float* __restrict__ B,
                                                       float* __restrict__ C,
                                                       int M, int N, int K)
{
    extern __shared__ __align__(16) char smem[];

    const int tid  = threadIdx.x;
    const int wid  = tid >> 5;
    const int lane = tid & 31;
    const int wm   = wid >> 2;     // 0..1  (64-row slab)
    const int wn   = wid & 3;      // 0..3  (32-col slab)
    const int gr   = lane >> 2;    // 0..7
    const int gc   = lane & 3;     // 0..3
    const int bm   = blockIdx.y * 128;
    const int bn   = blockIdx.x * 128;

    // load mapping: 1024 float4 chunks per tile, 4 per thread (A and B each)
    int ld_row[4], ld_ch[4];
    const float* pa[4];
    const float* pb[4];
#pragma unroll
    for (int i = 0; i < 4; ++i) {
        int idx = tid + i * 256;
        ld_row[i] = idx >> 3;
        ld_ch[i]  = idx & 7;
        pa[i] = A + (size_t)(bm + ld_row[i]) * K + ld_ch[i] * 4;
        pb[i] = B + (size_t)(bn + ld_row[i]) * K + ld_ch[i] * 4;
    }

    const int NIT = K >> 5;

    float4 ra[4], rb[4];
#pragma unroll
    for (int i = 0; i < 4; ++i) { ra[i] = *(const float4*)pa[i]; rb[i] = *(const float4*)pb[i]; }

    float acc[4][4][4];
#pragma unroll
    for (int mt = 0; mt < 4; ++mt)
#pragma unroll
        for (int nt = 0; nt < 4; ++nt)
#pragma unroll
            for (int r = 0; r < 4; ++r) acc[mt][nt][r] = 0.0f;

#pragma unroll 1
    for (int it = 0; it < NIT; ++it) {
        char* sb = smem + (it & 1) * STAGE_BYTES;

        // convert + store this iteration's tiles
#pragma unroll
        for (int i = 0; i < 4; ++i) {
            const int off = (ld_row[i] * PITCH + ld_ch[i] * 2) * 4;
            uint2 hi, lo;
            split4(ra[i], hi, lo);
            *(uint2*)(sb + ST_AHI + off) = hi;
            *(uint2*)(sb + ST_ALO + off) = lo;
            split4(rb[i], hi, lo);
            *(uint2*)(sb + ST_BHI + off) = hi;
            *(uint2*)(sb + ST_BLO + off) = lo;
        }

        // prefetch next iteration
        if (it + 1 < NIT) {
            const int koff = (it + 1) * 32;
#pragma unroll
            for (int i = 0; i < 4; ++i) {
                ra[i] = *(const float4*)(pa[i] + koff);
                rb[i] = *(const float4*)(pb[i] + koff);
            }
        }

        __syncthreads();

        const uint32_t* Ah = (const uint32_t*)(sb + ST_AHI);
        const uint32_t* Al = (const uint32_t*)(sb + ST_ALO);
        const uint32_t* Bh = (const uint32_t*)(sb + ST_BHI);
        const uint32_t* Bl = (const uint32_t*)(sb + ST_BLO);

#pragma unroll
        for (int ks = 0; ks < 2; ++ks) {     // two k16 substeps in BK=32
            const int jb = ks * 8 + gc;

            uint32_t b_hi[4][2], b_lo[4][2];
#pragma unroll
            for (int nt = 0; nt < 4; ++nt) {
                const int n0 = (wn * 32 + nt * 8 + gr) * PITCH;
                b_hi[nt][0] = Bh[n0 + jb];     b_hi[nt][1] = Bh[n0 + jb + 4];
                b_lo[nt][0] = Bl[n0 + jb];     b_lo[nt][1] = Bl[n0 + jb + 4];
            }

#pragma unroll
            for (int mt = 0; mt < 4; ++mt) {
                const int r0 = (wm * 64 + mt * 16 + gr) * PITCH;
                const int r8 = r0 + 8 * PITCH;
                uint32_t a_hi[4], a_lo[4];
                a_hi[0] = Ah[r0 + jb];     a_hi[1] = Ah[r8 + jb];
                a_hi[2] = Ah[r0 + jb + 4]; a_hi[3] = Ah[r8 + jb + 4];
                a_lo[0] = Al[r0 + jb];     a_lo[1] = Al[r8 + jb];
                a_lo[2] = Al[r0 + jb + 4]; a_lo[3] = Al[r8 + jb + 4];

#pragma unroll
                for (int nt = 0; nt < 4; ++nt) {
                    mma_bf16(acc[mt][nt], a_hi, b_hi[nt]);
                    mma_bf16(acc[mt][nt], a_hi, b_lo[nt]);
                    mma_bf16(acc[mt][nt], a_lo, b_hi[nt]);
                }
            }
        }
        __syncthreads();
    }

    // epilogue: fragment regs -> gmem (8B stores, coalesced within quads)
#pragma unroll
    for (int mt = 0; mt < 4; ++mt) {
        const int row = bm + wm * 64 + mt * 16 + gr;
#pragma unroll
        for (int nt = 0; nt < 4; ++nt) {
            const int col = bn + wn * 32 + nt * 8 + 2 * gc;
            *(float2*)&C[(size_t)row * N + col]       = make_float2(acc[mt][nt][0], acc[mt][nt][1]);
            *(float2*)&C[(size_t)(row + 8) * N + col] = make_float2(acc[mt][nt][2], acc[mt][nt][3]);
        }
    }
}

// ---------------------------------------------------------------------------
// RoPE in-place. data: [SEQ, nheads*128]. Position = seq index.
// ---------------------------------------------------------------------------
__global__ void rope_kernel(float* __restrict__ data, int nheads)
{
    int idx = blockIdx.x * blockDim.x + threadIdx.x;
    int total = SEQ * nheads * 64;
    if (idx >= total) return;
    int j = idx & 63;
    int h = (idx >> 6) % nheads;
    int s = idx / (64 * nheads);

    const float LOG2_THETA = 19.931568569324174f;   // log2(1e6)
    float inv = exp2f(-(float)j * (LOG2_THETA / 64.0f));
    float ang = (float)s * inv;
    float sn, cs;
    sincosf(ang, &sn, &cs);

    float* p = data + (size_t)s * (nheads * 128) + h * 128 + j;
    float x0 = p[0], x1 = p[64];
    p[0]  = x0 * cs - x1 * sn;
    p[64] = x1 * cs + x0 * sn;
}

// ---------------------------------------------------------------------------
// fp32 flash attention. BQ=BK=64, D=128. grid = (32 qblocks, 32 heads),
// 256 threads. Online softmax. Writes g_A[s, head*128 + d].
// ---------------------------------------------------------------------------
struct FlashSmem {
    float Q[64][129];
    float K[64][129];
    float V[64][132];
    float S[64][68];
    float m[64];
    float l[64];
    float alpha[64];
};

__global__ __launch_bounds__(256) void flash_attn()
{
    extern __shared__ char smem_raw[];
    FlashSmem* sh = (FlashSmem*)smem_raw;

    const int tid  = threadIdx.x;
    const int head = blockIdx.y;
    const int qb   = gridDim.x - 1 - blockIdx.x;
    const int kvh  = head >> 2;
    const int qbase = qb * 64;

    const int ti = tid >> 4, tj = tid & 15;
    const int r  = tid >> 2, c  = tid & 3;
    const int rr = tid >> 3, dc = tid & 7;

    for (int idx = tid; idx < 64 * 32; idx += 256) {
        int row = idx >> 5;
        int c4  = (idx & 31) * 4;
        float4 v = *(const float4*)&g_Q[(size_t)(qbase + row) * HID + head * HD + c4];
        sh->Q[row][c4 + 0] = v.x; sh->Q[row][c4 + 1] = v.y;
        sh->Q[row][c4 + 2] = v.z; sh->Q[row][c4 + 3] = v.w;
    }
    if (tid < 64) { sh->m[tid] = -1e30f; sh->l[tid] = 0.0f; }

    float acc0[16], acc1[16];
#pragma unroll
    for (int i = 0; i < 16; i++) { acc0[i] = 0.0f; acc1[i] = 0.0f; }

    __syncthreads();

    const float scale = 0.08838834764831845f;

    for (int kb = 0; kb <= qb; ++kb) {
        const int kbase = kb * 64;
        for (int idx = tid; idx < 64 * 32; idx += 256) {
            int row = idx >> 5;
            int c4  = (idx & 31) * 4;
            float4 vk = *(const float4*)&g_K[(size_t)(kbase + row) * KVD + kvh * HD + c4];
            sh->K[row][c4 + 0] = vk.x; sh->K[row][c4 + 1] = vk.y;
            sh->K[row][c4 + 2] = vk.z; sh->K[row][c4 + 3] = vk.w;
            float4 vv = *(const float4*)&g_V[(size_t)(kbase + row) * KVD + kvh * HD + c4];
            sh->V[row][c4 + 0] = vv.x; sh->V[row][c4 + 1] = vv.y;
            sh->V[row][c4 + 2] = vv.z; sh->V[row][c4 + 3] = vv.w;
        }
        __syncthreads();

        float s[4][4];
#pragma unroll
        for (int a = 0; a < 4; a++)
#pragma unroll
            for (int b = 0; b < 4; b++) s[a][b] = 0.0f;

#pragma unroll 4
        for (int d = 0; d < 128; ++d) {
            float qa[4], kv[4];
#pragma unroll
            for (int a = 0; a < 4; a++) qa[a] = sh->Q[ti * 4 + a][d];
#pragma unroll
            for (int b = 0; b < 4; b++) kv[b] = sh->K[tj * 4 + b][d];
#pragma unroll
            for (int a = 0; a < 4; a++)
#pragma unroll
                for (int b = 0; b < 4; b++)
                    s[a][b] = fmaf(qa[a], kv[b], s[a][b]);
        }

        const bool diag = (kb == qb);
#pragma unroll
        for (int a = 0; a < 4; a++)
#pragma unroll
            for (int b = 0; b < 4; b++) {
                float val = s[a][b] * scale;
                if (diag && (tj * 4 + b > ti * 4 + a)) val = -1e30f;
                sh->S[ti * 4 + a][tj * 4 + b] = val;
            }
        __syncthreads();

        float sv[16];
        float mloc = -1e30f;
#pragma unroll
        for (int j = 0; j < 16; j++) {
            sv[j] = sh->S[r][c * 16 + j];
            mloc = fmaxf(mloc, sv[j]);
        }
        mloc = fmaxf(mloc, __shfl_xor_sync(0xffffffffu, mloc, 1));
        mloc = fmaxf(mloc, __shfl_xor_sync(0xffffffffu, mloc, 2));
        float mo = sh->m[r];
        float mn = fmaxf(mo, mloc);
        float sum = 0.0f;
#pragma unroll
        for (int j = 0; j < 16; j++) {
            float p = __expf(sv[j] - mn);
            sum += p;
            sh->S[r][c * 16 + j] = p;
        }
        sum += __shfl_xor_sync(0xffffffffu, sum, 1);
        sum += __shfl_xor_sync(0xffffffffu, sum, 2);
        if (c == 0) {
            float al = __expf(mo - mn);
            sh->alpha[r] = al;
            sh->m[r] = mn;
            sh->l[r] = sh->l[r] * al + sum;
        }
        __syncthreads();

        float a0 = sh->alpha[rr], a1 = sh->alpha[rr + 32];
#pragma unroll
        for (int i = 0; i < 16; i++) { acc0[i] *= a0; acc1[i] *= a1; }

#pragma unroll 2
        for (int k = 0; k < 64; ++k) {
            float p0 = sh->S[rr][k];
            float p1 = sh->S[rr + 32][k];
            const float4* vp = (const float4*)&sh->V[k][dc * 16];
#pragma unroll
            for (int i4 = 0; i4 < 4; ++i4) {
                float4 v = vp[i4];
                acc0[i4 * 4 + 0] = fmaf(p0, v.x, acc0[i4 * 4 + 0]);
                acc0[i4 * 4 + 1] = fmaf(p0, v.y, acc0[i4 * 4 + 1]);
                acc0[i4 * 4 + 2] = fmaf(p0, v.z, acc0[i4 * 4 + 2]);
                acc0[i4 * 4 + 3] = fmaf(p0, v.w, acc0[i4 * 4 + 3]);
                acc1[i4 * 4 + 0] = fmaf(p1, v.x, acc1[i4 * 4 + 0]);
                acc1[i4 * 4 + 1] = fmaf(p1, v.y, acc1[i4 * 4 + 1]);
                acc1[i4 * 4 + 2] = fmaf(p1, v.z, acc1[i4 * 4 + 2]);
                acc1[i4 * 4 + 3] = fmaf(p1, v.w, acc1[i4 * 4 + 3]);
            }
        }
        __syncthreads();
    }

    float inv0 = 1.0f / sh->l[rr];
    float inv1 = 1.0f / sh->l[rr + 32];
    float* o0 = &g_A[(size_t)(qbase + rr) * HID + head * HD + dc * 16];
    float* o1 = &g_A[(size_t)(qbase + rr + 32) * HID + head * HD + dc * 16];
#pragma unroll
    for (int i4 = 0; i4 < 4; ++i4) {
        ((float4*)o0)[i4] = make_float4(acc0[i4 * 4 + 0] * inv0, acc0[i4 * 4 + 1] * inv0,
                                        acc0[i4 * 4 + 2] * inv0, acc0[i4 * 4 + 3] * inv0);
        ((float4*)o1)[i4] = make_float4(acc1[i4 * 4 + 0] * inv1, acc1[i4 * 4 + 1] * inv1,
                                        acc1[i4 * 4 + 2] * inv1, acc1[i4 * 4 + 3] * inv1);
    }
}

// ---------------------------------------------------------------------------
extern "C" void kernel_launch(void* const* d_in, const int* in_sizes, int n_in,
                              void* d_out, int out_size)
{
    const float* X  = (const float*)d_in[0];
    const float* Wq = (const float*)d_in[2];
    const float* Wk = (const float*)d_in[3];
    const float* Wv = (const float*)d_in[4];
    const float* Wo = (const float*)d_in[5];
    float* out = (float*)d_out;

    float *Qp, *Kp, *Vp, *Ap;
    cudaGetSymbolAddress((void**)&Qp, g_Q);
    cudaGetSymbolAddress((void**)&Kp, g_K);
    cudaGetSymbolAddress((void**)&Vp, g_V);
    cudaGetSymbolAddress((void**)&Ap, g_A);

    cudaFuncSetAttribute(mma_gemm_bf16x2, cudaFuncAttributeMaxDynamicSharedMemorySize,
                         GEMM_SMEM_BYTES);

    dim3 blk(256);
    // QKV projections (bf16x2 split-float mma)
    mma_gemm_bf16x2<<<dim3(HID / 128, SEQ / 128), blk, GEMM_SMEM_BYTES>>>(X, Wq, Qp, SEQ, HID, HID);
    mma_gemm_bf16x2<<<dim3(KVD / 128, SEQ / 128), blk, GEMM_SMEM_BYTES>>>(X, Wk, Kp, SEQ, KVD, HID);
    mma_gemm_bf16x2<<<dim3(KVD / 128, SEQ / 128), blk, GEMM_SMEM_BYTES>>>(X, Wv, Vp, SEQ, KVD, HID);

    // RoPE
    rope_kernel<<<(SEQ * NH * 64 + 255) / 256, 256>>>(Qp, NH);
    rope_kernel<<<(SEQ * NKV * 64 + 255) / 256, 256>>>(Kp, NKV);

    // Attention
    cudaFuncSetAttribute(flash_attn, cudaFuncAttributeMaxDynamicSharedMemorySize,
                         (int)sizeof(FlashSmem));
    flash_attn<<<dim3(SEQ / 64, NH), blk, sizeof(FlashSmem)>>>();

    // Output projection (bf16x2 split-float mma)
    mma_gemm_bf16x2<<<dim3(HID / 128, SEQ / 128), blk, GEMM_SMEM_BYTES>>>(Ap, Wo, out, SEQ, HID, HID);
}